// round 15
// baseline (speedup 1.0000x reference)
#include <cuda_runtime.h>
#include <cuda_fp16.h>
#include <math.h>
#include <stdint.h>

#define BATCH 512
#define CIN   1024
#define CMID  512
#define HW2   196
#define EMBD  1024
#define NCOL  (BATCH * HW2)   // 100352 = 784 * 128

// ---------------- scratch (device globals; no allocations allowed) ----------
__device__ float g_attr1[8 * 512];
__device__ float g_attr2[8 * 512];
__device__ float g_attlog[NCOL];
__device__ float g_feat[BATCH * 1024];
__device__ float g_bi[CMID];
__device__ __align__(16) __half g_Wc_h[CMID * CIN];
// tail-GEMM weights, fp16 hi/lo
__device__ __align__(16) __half g_w1h[512 * 1536], g_w1l[512 * 1536];
__device__ __align__(16) __half g_w2h[1024 * 512], g_w2l[1024 * 512];
__device__ __align__(16) __half g_w3h[1024 * 1024], g_w3l[1024 * 1024];
// tail-GEMM activations, fp16 hi/lo
__device__ __align__(16) __half g_in1h[512 * 1536], g_in1l[512 * 1536];
__device__ __align__(16) __half g_h1h[512 * 512],  g_h1l[512 * 512];
__device__ __align__(16) __half g_fmh[512 * 1024], g_fml[512 * 1024];

// ======================= PTX helpers (non-'a' features only) ================
__device__ __forceinline__ uint32_t smem_u32(const void* p) {
    uint32_t a;
    asm("{ .reg .u64 t; cvta.to.shared.u64 t, %1; cvt.u32.u64 %0, t; }" : "=r"(a) : "l"(p));
    return a;
}
#define CP_ASYNC16(dst, src) \
    asm volatile("cp.async.cg.shared.global [%0], [%1], 16;" :: "r"(dst), "l"(src) : "memory")
#define CP_COMMIT() asm volatile("cp.async.commit_group;" ::: "memory")
#define CP_WAIT(n)  asm volatile("cp.async.wait_group %0;" :: "n"(n) : "memory")

#define LDSM_X4(r0, r1, r2, r3, addr) \
    asm volatile("ldmatrix.sync.aligned.m8n8.x4.shared.b16 {%0,%1,%2,%3}, [%4];" \
                 : "=r"(r0), "=r"(r1), "=r"(r2), "=r"(r3) : "r"(addr))
#define LDSM_X4T(r0, r1, r2, r3, addr) \
    asm volatile("ldmatrix.sync.aligned.m8n8.x4.trans.shared.b16 {%0,%1,%2,%3}, [%4];" \
                 : "=r"(r0), "=r"(r1), "=r"(r2), "=r"(r3) : "r"(addr))

#define MMA16816(C, A, B0, B1) \
    asm volatile("mma.sync.aligned.m16n8k16.row.col.f32.f16.f16.f32 " \
                 "{%0,%1,%2,%3},{%4,%5,%6,%7},{%8,%9},{%0,%1,%2,%3};" \
                 : "+f"((C)[0]), "+f"((C)[1]), "+f"((C)[2]), "+f"((C)[3]) \
                 : "r"((A)[0]), "r"((A)[1]), "r"((A)[2]), "r"((A)[3]), "r"(B0), "r"(B1))

__device__ __forceinline__ float ftanh(float x) {
    float y;
    asm("tanh.approx.f32 %0, %1;" : "=f"(y) : "f"(x));
    return y;
}
__device__ __forceinline__ void split16(float v, __half& h, __half& l) {
    h = __float2half_rn(v);
    l = __float2half_rn(v - __half2float(h));
}
__device__ __forceinline__ uint2 cvt4(float4 f) {
    __half2 a = __floats2half2_rn(f.x, f.y);
    __half2 b = __floats2half2_rn(f.z, f.w);
    uint2 u;
    u.x = *(uint32_t*)&a;
    u.y = *(uint32_t*)&b;
    return u;
}

// ====== launch 1: zero attention logits =====================================
__global__ void zero_kernel() {
    int i = blockIdx.x * 256 + threadIdx.x;
    if (i < NCOL) g_attlog[i] = 0.f;
}

// ====== launch 2 (merged): fold BN into Wc->fp16 + wsplit ===================
__global__ void prep_kernel(const float* __restrict__ Wc, const float* __restrict__ bc,
                            const float* __restrict__ gamma, const float* __restrict__ beta,
                            const float* __restrict__ mean, const float* __restrict__ var,
                            const float* __restrict__ W1, const float* __restrict__ W2,
                            const float* __restrict__ W3) {
    int bid = blockIdx.x, tid = threadIdx.x;
    if (bid < 512) {
        int o = bid;
        float sc = gamma[o] * rsqrtf(var[o] + 1e-5f);
        if (tid == 0) g_bi[o] = (bc[o] - mean[o]) * sc + beta[o];
        float4 v = ((const float4*)(Wc + (size_t)o * CIN))[tid];
        __half2 h01 = __floats2half2_rn(v.x * sc, v.y * sc);
        __half2 h23 = __floats2half2_rn(v.z * sc, v.w * sc);
        uint2 u;
        u.x = *(uint32_t*)&h01;
        u.y = *(uint32_t*)&h23;
        ((uint2*)g_Wc_h)[o * 256 + tid] = u;
        return;
    }
    int wb = bid - 512;
    const float* src;
    __half *dh, *dl;
    int i;
    if (wb < 768)        { src = W1; dh = g_w1h; dl = g_w1l; i = wb * 256 + tid; }
    else if (wb < 1280)  { src = W2; dh = g_w2h; dl = g_w2l; i = (wb - 768) * 256 + tid; }
    else                 { src = W3; dh = g_w3h; dl = g_w3l; i = (wb - 1280) * 256 + tid; }
    float4 v = ((const float4*)src)[i];
    __half h0, h1, h2, h3, l0, l1, l2, l3;
    split16(v.x, h0, l0); split16(v.y, h1, l1);
    split16(v.z, h2, l2); split16(v.w, h3, l3);
    __half2 hh01 = __halves2half2(h0, h1), hh23 = __halves2half2(h2, h3);
    __half2 ll01 = __halves2half2(l0, l1), ll23 = __halves2half2(l2, l3);
    uint2 uh, ul;
    uh.x = *(uint32_t*)&hh01; uh.y = *(uint32_t*)&hh23;
    ul.x = *(uint32_t*)&ll01; ul.y = *(uint32_t*)&ll23;
    ((uint2*)dh)[i] = uh;
    ((uint2*)dl)[i] = ul;
}

// ====== launch 3: attr tables, 64 CTAs ======================================
__global__ void attr_kernel(const float* __restrict__ emb,
                            const float* __restrict__ Wt1, const float* __restrict__ bt1,
                            const float* __restrict__ Wt2, const float* __restrict__ bt2) {
    int a = blockIdx.x;
    int og = blockIdx.y;
    __shared__ float e[512];
    int tid = threadIdx.x;
    e[tid]       = emb[a * 512 + tid];
    e[tid + 256] = emb[a * 512 + tid + 256];
    __syncthreads();
    int warp = tid >> 5, lane = tid & 31;
    int o = og * 64 + warp * 8;
    #pragma unroll
    for (int t = 0; t < 8; t++, o++) {
        float s1 = 0.f, s2 = 0.f;
        #pragma unroll
        for (int k = lane; k < 512; k += 32) {
            float ev = e[k];
            s1 = fmaf(ev, Wt1[o * 512 + k], s1);
            s2 = fmaf(ev, Wt2[o * 512 + k], s2);
        }
        #pragma unroll
        for (int off = 16; off; off >>= 1) {
            s1 += __shfl_down_sync(0xffffffffu, s1, off);
            s2 += __shfl_down_sync(0xffffffffu, s2, off);
        }
        if (lane == 0) {
            g_attr1[a * 512 + o] = tanhf(s1 + bt1[o]);
            g_attr2[a * 512 + o] = fmaxf(s2 + bt2[o], 0.f);
        }
    }
}

// ====== launch 4 (PROFILED): HMMA conv+BN+tanh+attn dot, fp32-x direct ======
// B loaded straight from fp32 x (LDG->cvt->STS, double buffer); x_prep gone.
// CTA 128M x 128N, 4 warps 2x2 (warp 64x64), K chunk 32, 2 smem buffers.
#define ST_A   10240
#define ST_B   8704
#define ST_BYTES (ST_A + ST_B)        // 18944
#define CONV_SMEM (2 * ST_BYTES)      // 37888

__global__ void __launch_bounds__(128, 2) conv_att_hmma(const float* __restrict__ x,
                                                        const int* __restrict__ cidx) {
    extern __shared__ char smem[];
    uint32_t sb = smem_u32(smem);
    int tid = threadIdx.x, wid = tid >> 5, lane = tid & 31;
    int wm = wid & 1, wn = wid >> 1;
    int m0 = blockIdx.x * 128;
    int n0 = blockIdx.y * 128;

    // ---- A: 4 granules of 16B from g_Wc_h (fp16, L2-resident) ----
    uint32_t a_soff[4], a_dst[4];
    #pragma unroll
    for (int t = 0; t < 4; t++) {
        int row = t * 32 + (tid >> 2), ch = tid & 3;
        a_soff[t] = (uint32_t)((m0 + row) * CIN + ch * 8);
        a_dst[t]  = (uint32_t)(row * 80 + ch * 16);
    }
    // ---- B: 8 granules of float4 from fp32 x ----
    const float4* b_src[8];
    uint32_t b_dst[8];
    {
        int col4 = tid & 31;
        int n = n0 + col4 * 4;
        int bcol = n / HW2;
        int hw = n - bcol * HW2;
        #pragma unroll
        for (int j = 0; j < 8; j++) {
            int krow = j * 4 + (tid >> 5);
            b_src[j] = (const float4*)x + ((size_t)(bcol * 1024 + krow) * 49 + (hw >> 2));
            b_dst[j] = ST_A + (uint32_t)(krow * 272 + col4 * 8);
        }
    }

    float acc[4][8][4];
    #pragma unroll
    for (int mi = 0; mi < 4; mi++)
        #pragma unroll
        for (int nj = 0; nj < 8; nj++)
            #pragma unroll
            for (int r = 0; r < 4; r++) acc[mi][nj][r] = 0.f;

    uint32_t a_lds = sb + (uint32_t)(wm * 64 + (lane & 15)) * 80 + ((lane >> 4) & 1) * 16;
    uint32_t b_lds = sb + ST_A + (uint32_t)(lane & 15) * 272 +
                     (uint32_t)(wn * 64 + ((lane >> 4) & 1) * 8) * 2;

    // ---- prologue: chunk0 -> buf0; chunk1 staged in regs ----
    uint4 ar[4];
    uint2 br[8];
    #pragma unroll
    for (int t = 0; t < 4; t++) ar[t] = __ldg((const uint4*)(g_Wc_h + a_soff[t]));
    #pragma unroll
    for (int j = 0; j < 8; j++) br[j] = cvt4(__ldg(b_src[j]));
    #pragma unroll
    for (int t = 0; t < 4; t++) *(uint4*)(smem + a_dst[t]) = ar[t];
    #pragma unroll
    for (int j = 0; j < 8; j++) *(uint2*)(smem + b_dst[j]) = br[j];
    #pragma unroll
    for (int t = 0; t < 4; t++) ar[t] = __ldg((const uint4*)(g_Wc_h + a_soff[t] + 32));
    #pragma unroll
    for (int j = 0; j < 8; j++) br[j] = cvt4(__ldg(b_src[j] + 1568));
    __syncthreads();

    for (int s = 0; s < 32; s++) {
        uint32_t cbuf = (uint32_t)(s & 1) * ST_BYTES;
        uint32_t nbuf = (uint32_t)((s + 1) & 1) * ST_BYTES;
        if (s < 31) {
            // store staged chunk s+1 (its buffer was fully consumed in iter s-1)
            #pragma unroll
            for (int t = 0; t < 4; t++) *(uint4*)(smem + nbuf + a_dst[t]) = ar[t];
            #pragma unroll
            for (int j = 0; j < 8; j++) *(uint2*)(smem + nbuf + b_dst[j]) = br[j];
        }
        if (s < 30) {
            // prefetch chunk s+2 into regs (overlaps compute below)
            uint32_t ka = (uint32_t)(s + 2) * 32;
            uint32_t kb = (uint32_t)(s + 2) * 1568;
            #pragma unroll
            for (int t = 0; t < 4; t++) ar[t] = __ldg((const uint4*)(g_Wc_h + a_soff[t] + ka));
            #pragma unroll
            for (int j = 0; j < 8; j++) br[j] = cvt4(__ldg(b_src[j] + kb));
        }

        #pragma unroll
        for (int ks = 0; ks < 2; ks++) {
            uint32_t bfr[4][4];
            uint32_t baddr = b_lds + cbuf + (uint32_t)(ks * 16) * 272;
            #pragma unroll
            for (int bq = 0; bq < 4; bq++)
                LDSM_X4T(bfr[bq][0], bfr[bq][1], bfr[bq][2], bfr[bq][3], baddr + bq * 32);
            #pragma unroll
            for (int mi = 0; mi < 4; mi++) {
                uint32_t ah[4];
                uint32_t aaddr = a_lds + cbuf + (uint32_t)(mi * 16) * 80 + ks * 32;
                LDSM_X4(ah[0], ah[1], ah[2], ah[3], aaddr);
                #pragma unroll
                for (int bq = 0; bq < 4; bq++) {
                    MMA16816(acc[mi][bq * 2 + 0], ah, bfr[bq][0], bfr[bq][1]);
                    MMA16816(acc[mi][bq * 2 + 1], ah, bfr[bq][2], bfr[bq][3]);
                }
            }
        }
        __syncthreads();
    }

    // ---- epilogue: logits[n] += sum_m attr1[c(n)][m] * tanh(D[m][n]+bi[m]) ----
    int b0i = n0 / HW2;
    int ncut = (b0i + 1) * HW2;
    int b1i = (ncut < n0 + 128) ? b0i + 1 : b0i;
    int c0i = cidx[b0i], c1i = cidx[b1i];
    int r0 = lane >> 2;
    int colE = (lane & 3) * 2;

    float accE[8], accO[8];
    #pragma unroll
    for (int nj = 0; nj < 8; nj++) { accE[nj] = 0.f; accO[nj] = 0.f; }
    #pragma unroll
    for (int mi = 0; mi < 4; mi++) {
        int mA = m0 + wm * 64 + mi * 16 + r0;
        int mB = mA + 8;
        float biA = g_bi[mA], biB = g_bi[mB];
        float a0A = g_attr1[c0i * 512 + mA], a1A = g_attr1[c1i * 512 + mA];
        float a0B = g_attr1[c0i * 512 + mB], a1B = g_attr1[c1i * 512 + mB];
        #pragma unroll
        for (int nj = 0; nj < 8; nj++) {
            int colg = n0 + wn * 64 + nj * 8 + colE;
            float awAe = (colg < ncut) ? a0A : a1A;
            float awBe = (colg < ncut) ? a0B : a1B;
            float awAo = (colg + 1 < ncut) ? a0A : a1A;
            float awBo = (colg + 1 < ncut) ? a0B : a1B;
            accE[nj] += awAe * ftanh(acc[mi][nj][0] + biA) + awBe * ftanh(acc[mi][nj][2] + biB);
            accO[nj] += awAo * ftanh(acc[mi][nj][1] + biA) + awBo * ftanh(acc[mi][nj][3] + biB);
        }
    }
    #pragma unroll
    for (int off = 4; off <= 16; off <<= 1) {
        #pragma unroll
        for (int nj = 0; nj < 8; nj++) {
            accE[nj] += __shfl_xor_sync(0xffffffffu, accE[nj], off);
            accO[nj] += __shfl_xor_sync(0xffffffffu, accO[nj], off);
        }
    }
    float* sred = (float*)smem;
    if (lane < 4) {
        #pragma unroll
        for (int nj = 0; nj < 8; nj++) {
            sred[wid * 64 + nj * 8 + colE]     = accE[nj];
            sred[wid * 64 + nj * 8 + colE + 1] = accO[nj];
        }
    }
    __syncthreads();
    if (tid < 128) {
        int wn2 = tid >> 6, cl = tid & 63;
        float t = sred[(wn2 * 2) * 64 + cl] + sred[(wn2 * 2 + 1) * 64 + cl];
        atomicAdd(&g_attlog[n0 + tid], t);
    }
}

// ==== launch 5: softmax + feat (reads fp32 x, contiguous) + G1-input build ==
__global__ void feat_kernel(const float* __restrict__ x, const int* __restrict__ cidx) {
    int b = blockIdx.x, tid = threadIdx.x;
    __shared__ float sh[256];
    __shared__ float p[HW2 + 12];
    float v = (tid < HW2) ? g_attlog[b * HW2 + tid] * 0.044194173824159216f : -1e30f;
    sh[tid] = v;
    __syncthreads();
    for (int s = 128; s; s >>= 1) {
        if (tid < s) sh[tid] = fmaxf(sh[tid], sh[tid + s]);
        __syncthreads();
    }
    float mx = sh[0];
    __syncthreads();
    float e = (tid < HW2) ? __expf(v - mx) : 0.f;
    sh[tid] = e;
    __syncthreads();
    for (int s = 128; s; s >>= 1) {
        if (tid < s) sh[tid] += sh[tid + s];
        __syncthreads();
    }
    float inv = 1.f / sh[0];
    if (tid < 208) p[tid] = (tid < HW2) ? e * inv : 0.f;
    __syncthreads();

    int warp = tid >> 5, lane = tid & 31;
    const float4* xb = (const float4*)(x + (size_t)b * (CIN * HW2));
    for (int c = warp; c < CIN; c += 8) {
        const float4* row = xb + c * 49;
        float sum = 0.f;
        #pragma unroll
        for (int ch = lane; ch < 49; ch += 32) {
            float4 f = row[ch];
            int hw = ch * 4;
            sum = fmaf(f.x, p[hw + 0], sum);
            sum = fmaf(f.y, p[hw + 1], sum);
            sum = fmaf(f.z, p[hw + 2], sum);
            sum = fmaf(f.w, p[hw + 3], sum);
        }
        #pragma unroll
        for (int off = 16; off; off >>= 1)
            sum += __shfl_down_sync(0xffffffffu, sum, off);
        if (lane == 0) {
            g_feat[b * CIN + c] = sum;
            __half h, l;
            split16(sum, h, l);
            g_in1h[b * 1536 + c] = h;
            g_in1l[b * 1536 + c] = l;
        }
    }
    int ci = cidx[b];
    for (int j = tid; j < 512; j += 256) {
        float a = g_attr2[ci * 512 + j];
        __half h, l;
        split16(a, h, l);
        g_in1h[b * 1536 + 1024 + j] = h;
        g_in1l[b * 1536 + 1024 + j] = l;
    }
}

// =========== HMMA tail GEMM: C = act(A @ W^T + bias), 3-product split =======
#define GT_STAGE 15360
template <int EPI, int N, int K>
__global__ void __launch_bounds__(128, 4) gemmH_kernel(const float* __restrict__ bias,
                                                       float* __restrict__ outp) {
    const __half* Ah = (EPI == 0) ? g_in1h : (EPI == 1) ? g_h1h : g_fmh;
    const __half* Al = (EPI == 0) ? g_in1l : (EPI == 1) ? g_h1l : g_fml;
    const __half* Wh = (EPI == 0) ? g_w1h : (EPI == 1) ? g_w2h : g_w3h;
    const __half* Wl = (EPI == 0) ? g_w1l : (EPI == 1) ? g_w2l : g_w3l;

    extern __shared__ char smem[];
    uint32_t sb = smem_u32(smem);
    int tid = threadIdx.x, wid = tid >> 5, lane = tid & 31;
    int n0 = blockIdx.x * 64;
    int m0 = blockIdx.y * 32;

    int aRow = tid >> 2, aCh = tid & 3;
    const __half* srcAh = Ah + (size_t)(m0 + aRow) * K + aCh * 8;
    const __half* srcAl = Al + (size_t)(m0 + aRow) * K + aCh * 8;
    uint32_t dstAh = (uint32_t)(aRow * 80 + aCh * 16);
    uint32_t dstAl = 2560 + dstAh;
    const __half* srcWh0 = Wh + (size_t)(n0 + aRow) * K + aCh * 8;
    const __half* srcWh1 = Wh + (size_t)(n0 + 32 + aRow) * K + aCh * 8;
    const __half* srcWl0 = Wl + (size_t)(n0 + aRow) * K + aCh * 8;
    const __half* srcWl1 = Wl + (size_t)(n0 + 32 + aRow) * K + aCh * 8;
    uint32_t dstWh0 = 5120 + (uint32_t)(aRow * 80 + aCh * 16);
    uint32_t dstWh1 = dstWh0 + 32 * 80;
    uint32_t dstWl0 = dstWh0 + 5120;
    uint32_t dstWl1 = dstWh1 + 5120;

    float acc[2][2][4];
    #pragma unroll
    for (int mi = 0; mi < 2; mi++)
        #pragma unroll
        for (int nj = 0; nj < 2; nj++)
            #pragma unroll
            for (int r = 0; r < 4; r++) acc[mi][nj][r] = 0.f;

    uint32_t a_lds = sb + (uint32_t)(lane & 15) * 80 + ((lane >> 4) & 1) * 16;
    uint32_t w_lds = sb + 5120 + (uint32_t)(wid * 16 + (lane & 15)) * 80 + ((lane >> 4) & 1) * 16;

    const int NC = K / 32;
    #pragma unroll
    for (int st = 0; st < 2; st++) {
        uint32_t buf = (uint32_t)st * GT_STAGE;
        uint32_t ka = (uint32_t)st * 32;
        CP_ASYNC16(dstAh + sb + buf, srcAh + ka);
        CP_ASYNC16(dstAl + sb + buf, srcAl + ka);
        CP_ASYNC16(dstWh0 + sb + buf, srcWh0 + ka);
        CP_ASYNC16(dstWh1 + sb + buf, srcWh1 + ka);
        CP_ASYNC16(dstWl0 + sb + buf, srcWl0 + ka);
        CP_ASYNC16(dstWl1 + sb + buf, srcWl1 + ka);
        CP_COMMIT();
    }

    int cstage = 0;
    for (int s = 0; s < NC; s++) {
        if (s < NC - 1) { CP_WAIT(1); } else { CP_WAIT(0); }
        __syncthreads();

        if (s < NC - 2) {
            int pst = cstage + 2; if (pst >= 3) pst -= 3;
            uint32_t buf = (uint32_t)pst * GT_STAGE;
            uint32_t ka = (uint32_t)(s + 2) * 32;
            CP_ASYNC16(dstAh + sb + buf, srcAh + ka);
            CP_ASYNC16(dstAl + sb + buf, srcAl + ka);
            CP_ASYNC16(dstWh0 + sb + buf, srcWh0 + ka);
            CP_ASYNC16(dstWh1 + sb + buf, srcWh1 + ka);
            CP_ASYNC16(dstWl0 + sb + buf, srcWl0 + ka);
            CP_ASYNC16(dstWl1 + sb + buf, srcWl1 + ka);
            CP_COMMIT();
        }

        uint32_t cbuf = (uint32_t)cstage * GT_STAGE;
        #pragma unroll
        for (int ks = 0; ks < 2; ks++) {
            uint32_t wh[4], wl[4];
            uint32_t waddr = w_lds + cbuf + ks * 32;
            LDSM_X4(wh[0], wh[1], wh[2], wh[3], waddr);
            LDSM_X4(wl[0], wl[1], wl[2], wl[3], waddr + 5120);
            #pragma unroll
            for (int mi = 0; mi < 2; mi++) {
                uint32_t ah[4], al[4];
                uint32_t aaddr = a_lds + cbuf + (uint32_t)(mi * 16) * 80 + ks * 32;
                LDSM_X4(ah[0], ah[1], ah[2], ah[3], aaddr);
                LDSM_X4(al[0], al[1], al[2], al[3], aaddr + 2560);
                MMA16816(acc[mi][0], ah, wh[0], wh[2]);
                MMA16816(acc[mi][1], ah, wh[1], wh[3]);
                MMA16816(acc[mi][0], ah, wl[0], wl[2]);
                MMA16816(acc[mi][1], ah, wl[1], wl[3]);
                MMA16816(acc[mi][0], al, wh[0], wh[2]);
                MMA16816(acc[mi][1], al, wh[1], wh[3]);
            }
        }
        if (++cstage == 3) cstage = 0;
    }

    int r0 = lane >> 2;
    int cb = (lane & 3) * 2;
    #pragma unroll
    for (int nj = 0; nj < 2; nj++) {
        int gcol = n0 + wid * 16 + nj * 8 + cb;
        float bv0 = bias[gcol], bv1 = bias[gcol + 1];
        #pragma unroll
        for (int mi = 0; mi < 2; mi++) {
            #pragma unroll
            for (int rh = 0; rh < 2; rh++) {
                int row = m0 + mi * 16 + r0 + rh * 8;
                float v0 = acc[mi][nj][rh * 2 + 0] + bv0;
                float v1 = acc[mi][nj][rh * 2 + 1] + bv1;
                if (EPI == 0) {
                    v0 = fmaxf(v0, 0.f); v1 = fmaxf(v1, 0.f);
                    __half h0, l0, h1, l1;
                    split16(v0, h0, l0); split16(v1, h1, l1);
                    *(__half2*)(g_h1h + (size_t)row * N + gcol) = __halves2half2(h0, h1);
                    *(__half2*)(g_h1l + (size_t)row * N + gcol) = __halves2half2(l0, l1);
                } else if (EPI == 1) {
                    float s0 = 1.f / (1.f + __expf(-v0));
                    float s1 = 1.f / (1.f + __expf(-v1));
                    float p0 = s0 * g_feat[(size_t)row * 1024 + gcol];
                    float p1 = s1 * g_feat[(size_t)row * 1024 + gcol + 1];
                    __half h0, l0, h1, l1;
                    split16(p0, h0, l0); split16(p1, h1, l1);
                    *(__half2*)(g_fmh + (size_t)row * N + gcol) = __halves2half2(h0, h1);
                    *(__half2*)(g_fml + (size_t)row * N + gcol) = __halves2half2(l0, l1);
                } else {
                    *(float2*)(outp + (size_t)row * N + gcol) = make_float2(v0, v1);
                }
            }
        }
    }
}

// ---------------- row-wise L2 normalize in place ----------------------------
__global__ void l2norm_kernel(float* __restrict__ out) {
    int b = blockIdx.x, tid = threadIdx.x;
    __shared__ float sh[256];
    float s = 0.f;
    for (int i = tid; i < EMBD; i += 256) {
        float v = out[(size_t)b * EMBD + i];
        s = fmaf(v, v, s);
    }
    sh[tid] = s;
    __syncthreads();
    for (int st = 128; st; st >>= 1) {
        if (tid < st) sh[tid] += sh[tid + st];
        __syncthreads();
    }
    float inv = 1.f / sqrtf(sh[0]);
    for (int i = tid; i < EMBD; i += 256) out[(size_t)b * EMBD + i] *= inv;
}

// ---------------- launch ----------------------------------------------------
extern "C" void kernel_launch(void* const* d_in, const int* in_sizes, int n_in,
                              void* d_out, int out_size) {
    const float* x        = (const float*)d_in[0];
    const int*   c        = (const int*)  d_in[1];
    const float* attr_emb = (const float*)d_in[2];
    const float* Wt1      = (const float*)d_in[3];
    const float* bt1      = (const float*)d_in[4];
    const float* Wc       = (const float*)d_in[5];
    const float* bc       = (const float*)d_in[6];
    const float* bn_gamma = (const float*)d_in[7];
    const float* bn_beta  = (const float*)d_in[8];
    const float* bn_mean  = (const float*)d_in[9];
    const float* bn_var   = (const float*)d_in[10];
    const float* Wt2      = (const float*)d_in[11];
    const float* bt2      = (const float*)d_in[12];
    const float* W1       = (const float*)d_in[13];
    const float* b1       = (const float*)d_in[14];
    const float* W2       = (const float*)d_in[15];
    const float* b2       = (const float*)d_in[16];
    const float* Wf       = (const float*)d_in[17];
    const float* bf       = (const float*)d_in[18];
    float* out = (float*)d_out;

    static bool attr_set = false;
    if (!attr_set) {
        cudaFuncSetAttribute(conv_att_hmma, cudaFuncAttributeMaxDynamicSharedMemorySize, CONV_SMEM);
        attr_set = true;
    }

    zero_kernel<<<(NCOL + 255) / 256, 256>>>();                                               // 1
    prep_kernel<<<512 + 2304, 256>>>(Wc, bc, bn_gamma, bn_beta, bn_mean, bn_var, W1, W2, Wf); // 2
    attr_kernel<<<dim3(8, 8), 256>>>(attr_emb, Wt1, bt1, Wt2, bt2);                           // 3
    conv_att_hmma<<<dim3(4, NCOL / 128), 128, CONV_SMEM>>>(x, c);                             // 4 <- ncu
    feat_kernel<<<BATCH, 256>>>(x, c);                                                        // 5
    gemmH_kernel<0, 512, 1536><<<dim3(512 / 64, BATCH / 32), 128, 3 * GT_STAGE>>>(b1, nullptr);
    gemmH_kernel<1, 1024, 512><<<dim3(1024 / 64, BATCH / 32), 128, 3 * GT_STAGE>>>(b2, nullptr);
    gemmH_kernel<2, 1024, 1024><<<dim3(1024 / 64, BATCH / 32), 128, 3 * GT_STAGE>>>(bf, out);
    l2norm_kernel<<<BATCH, 256>>>(out);
}

// round 16
// speedup vs baseline: 1.2028x; 1.2028x over previous
#include <cuda_runtime.h>
#include <cuda_fp16.h>
#include <math.h>
#include <stdint.h>

#define BATCH 512
#define CIN   1024
#define CMID  512
#define HW2   196
#define EMBD  1024
#define NCOL  (BATCH * HW2)   // 100352 = 784 * 128

// ---------------- scratch (device globals; no allocations allowed) ----------
__device__ float g_attr1[8 * 512];
__device__ float g_attr2[8 * 512];
__device__ float g_attlog[NCOL];
__device__ float g_attp[NCOL];
__device__ float g_feat[BATCH * 1024];
__device__ float g_bi[CMID];
__device__ __align__(16) __half g_Wc_h[CMID * CIN];
__device__ __align__(16) __half g_xh[(size_t)CIN * NCOL];   // x^T [K][N] fp16
// tail-GEMM weights, fp16 hi/lo
__device__ __align__(16) __half g_w1h[512 * 1536], g_w1l[512 * 1536];
__device__ __align__(16) __half g_w2h[1024 * 512], g_w2l[1024 * 512];
__device__ __align__(16) __half g_w3h[1024 * 1024], g_w3l[1024 * 1024];
// tail-GEMM activations, fp16 hi/lo
__device__ __align__(16) __half g_in1h[512 * 1536], g_in1l[512 * 1536];
__device__ __align__(16) __half g_h1h[512 * 512],  g_h1l[512 * 512];
__device__ __align__(16) __half g_fmh[512 * 1024], g_fml[512 * 1024];

// ======================= PTX helpers (non-'a' features only) ================
__device__ __forceinline__ uint32_t smem_u32(const void* p) {
    uint32_t a;
    asm("{ .reg .u64 t; cvta.to.shared.u64 t, %1; cvt.u32.u64 %0, t; }" : "=r"(a) : "l"(p));
    return a;
}
#define CP_ASYNC16(dst, src) \
    asm volatile("cp.async.cg.shared.global [%0], [%1], 16;" :: "r"(dst), "l"(src) : "memory")
#define CP_COMMIT() asm volatile("cp.async.commit_group;" ::: "memory")
#define CP_WAIT(n)  asm volatile("cp.async.wait_group %0;" :: "n"(n) : "memory")

#define LDSM_X4(r0, r1, r2, r3, addr) \
    asm volatile("ldmatrix.sync.aligned.m8n8.x4.shared.b16 {%0,%1,%2,%3}, [%4];" \
                 : "=r"(r0), "=r"(r1), "=r"(r2), "=r"(r3) : "r"(addr))
#define LDSM_X4T(r0, r1, r2, r3, addr) \
    asm volatile("ldmatrix.sync.aligned.m8n8.x4.trans.shared.b16 {%0,%1,%2,%3}, [%4];" \
                 : "=r"(r0), "=r"(r1), "=r"(r2), "=r"(r3) : "r"(addr))

#define MMA16816(C, A, B0, B1) \
    asm volatile("mma.sync.aligned.m16n8k16.row.col.f32.f16.f16.f32 " \
                 "{%0,%1,%2,%3},{%4,%5,%6,%7},{%8,%9},{%0,%1,%2,%3};" \
                 : "+f"((C)[0]), "+f"((C)[1]), "+f"((C)[2]), "+f"((C)[3]) \
                 : "r"((A)[0]), "r"((A)[1]), "r"((A)[2]), "r"((A)[3]), "r"(B0), "r"(B1))

__device__ __forceinline__ float ftanh(float x) {
    float y;
    asm("tanh.approx.f32 %0, %1;" : "=f"(y) : "f"(x));
    return y;
}
__device__ __forceinline__ void split16(float v, __half& h, __half& l) {
    h = __float2half_rn(v);
    l = __float2half_rn(v - __half2float(h));
}

// ====== launch 1 (merged): zero attlog + fold BN into Wc->fp16 + wsplit =====
__global__ void prep_kernel(const float* __restrict__ Wc, const float* __restrict__ bc,
                            const float* __restrict__ gamma, const float* __restrict__ beta,
                            const float* __restrict__ mean, const float* __restrict__ var,
                            const float* __restrict__ W1, const float* __restrict__ W2,
                            const float* __restrict__ W3) {
    int bid = blockIdx.x, tid = threadIdx.x;
    if (bid < 512) {
        int o = bid;
        int zi = o * 256 + tid;
        if (zi < NCOL) g_attlog[zi] = 0.f;
        float sc = gamma[o] * rsqrtf(var[o] + 1e-5f);
        if (tid == 0) g_bi[o] = (bc[o] - mean[o]) * sc + beta[o];
        float4 v = ((const float4*)(Wc + (size_t)o * CIN))[tid];
        __half2 h01 = __floats2half2_rn(v.x * sc, v.y * sc);
        __half2 h23 = __floats2half2_rn(v.z * sc, v.w * sc);
        uint2 u;
        u.x = *(uint32_t*)&h01;
        u.y = *(uint32_t*)&h23;
        ((uint2*)g_Wc_h)[o * 256 + tid] = u;
        return;
    }
    int wb = bid - 512;
    const float* src;
    __half *dh, *dl;
    int i;
    if (wb < 768)        { src = W1; dh = g_w1h; dl = g_w1l; i = wb * 256 + tid; }
    else if (wb < 1280)  { src = W2; dh = g_w2h; dl = g_w2l; i = (wb - 768) * 256 + tid; }
    else                 { src = W3; dh = g_w3h; dl = g_w3l; i = (wb - 1280) * 256 + tid; }
    float4 v = ((const float4*)src)[i];
    __half h0, h1, h2, h3, l0, l1, l2, l3;
    split16(v.x, h0, l0); split16(v.y, h1, l1);
    split16(v.z, h2, l2); split16(v.w, h3, l3);
    __half2 hh01 = __halves2half2(h0, h1), hh23 = __halves2half2(h2, h3);
    __half2 ll01 = __halves2half2(l0, l1), ll23 = __halves2half2(l2, l3);
    uint2 uh, ul;
    uh.x = *(uint32_t*)&hh01; uh.y = *(uint32_t*)&hh23;
    ul.x = *(uint32_t*)&ll01; ul.y = *(uint32_t*)&ll23;
    ((uint2*)dh)[i] = uh;
    ((uint2*)dl)[i] = ul;
}

// ====== launch 2: attr tables, 64 CTAs ======================================
__global__ void attr_kernel(const float* __restrict__ emb,
                            const float* __restrict__ Wt1, const float* __restrict__ bt1,
                            const float* __restrict__ Wt2, const float* __restrict__ bt2) {
    int a = blockIdx.x;
    int og = blockIdx.y;
    __shared__ float e[512];
    int tid = threadIdx.x;
    e[tid]       = emb[a * 512 + tid];
    e[tid + 256] = emb[a * 512 + tid + 256];
    __syncthreads();
    int warp = tid >> 5, lane = tid & 31;
    int o = og * 64 + warp * 8;
    #pragma unroll
    for (int t = 0; t < 8; t++, o++) {
        float s1 = 0.f, s2 = 0.f;
        #pragma unroll
        for (int k = lane; k < 512; k += 32) {
            float ev = e[k];
            s1 = fmaf(ev, Wt1[o * 512 + k], s1);
            s2 = fmaf(ev, Wt2[o * 512 + k], s2);
        }
        #pragma unroll
        for (int off = 16; off; off >>= 1) {
            s1 += __shfl_down_sync(0xffffffffu, s1, off);
            s2 += __shfl_down_sync(0xffffffffu, s2, off);
        }
        if (lane == 0) {
            g_attr1[a * 512 + o] = tanhf(s1 + bt1[o]);
            g_attr2[a * 512 + o] = fmaxf(s2 + bt2[o], 0.f);
        }
    }
}

// ====== launch 3: transpose x to [K][N] fp16 ================================
__global__ void x_prep_kernel(const float* __restrict__ x) {
    int g = blockIdx.x * 256 + threadIdx.x;
    int row = g / 49;
    int q = g - row * 49;
    int b = row >> 10, k = row & 1023;
    float4 v = ((const float4*)x)[(size_t)row * 49 + q];
    __half2 h01 = __floats2half2_rn(v.x, v.y);
    __half2 h23 = __floats2half2_rn(v.z, v.w);
    uint2 u;
    u.x = *(uint32_t*)&h01;
    u.y = *(uint32_t*)&h23;
    *(uint2*)(g_xh + (size_t)k * NCOL + b * HW2 + q * 4) = u;
}

// ====== launch 4 (PROFILED): HMMA conv (R14 form: 5-stage K32 cp.async) =====
#define ST_A   10240
#define ST_B   8704
#define ST_BYTES (ST_A + ST_B)        // 18944
#define NSTAGE 5
#define CONV_SMEM (NSTAGE * ST_BYTES) // 94720

__global__ void __launch_bounds__(128, 2) conv_att_hmma(const int* __restrict__ cidx) {
    extern __shared__ char smem[];
    uint32_t sb = smem_u32(smem);
    int tid = threadIdx.x, wid = tid >> 5, lane = tid & 31;
    int wm = wid & 1, wn = wid >> 1;
    int m0 = blockIdx.x * 128;
    int n0 = blockIdx.y * 128;

    uint32_t a_soff[4], a_doff[4];
    #pragma unroll
    for (int t = 0; t < 4; t++) {
        int i = t * 128 + tid;
        int row = i >> 2, ch = i & 3;
        a_soff[t] = (uint32_t)((m0 + row) * CIN + ch * 8);
        a_doff[t] = (uint32_t)(row * 80 + ch * 16);
    }
    uint32_t b_soff[4], b_doff[4];
    #pragma unroll
    for (int t = 0; t < 4; t++) {
        int i = t * 128 + tid;
        int krow = i >> 4, bch = i & 15;
        b_soff[t] = (uint32_t)krow * NCOL + (uint32_t)(n0 + bch * 8);
        b_doff[t] = ST_A + (uint32_t)(krow * 272 + bch * 16);
    }

    float acc[4][8][4];
    #pragma unroll
    for (int mi = 0; mi < 4; mi++)
        #pragma unroll
        for (int nj = 0; nj < 8; nj++)
            #pragma unroll
            for (int r = 0; r < 4; r++) acc[mi][nj][r] = 0.f;

    uint32_t a_lds = sb + (uint32_t)(wm * 64 + (lane & 15)) * 80 + ((lane >> 4) & 1) * 16;
    uint32_t b_lds = sb + ST_A + (uint32_t)(lane & 15) * 272 +
                     (uint32_t)(wn * 64 + ((lane >> 4) & 1) * 8) * 2;

    #pragma unroll
    for (int st = 0; st < 4; st++) {
        uint32_t buf = (uint32_t)st * ST_BYTES;
        uint32_t ka = (uint32_t)st * 32;
        size_t kb = (size_t)st * 32 * NCOL;
        #pragma unroll
        for (int t = 0; t < 4; t++) CP_ASYNC16(sb + a_doff[t] + buf, g_Wc_h + a_soff[t] + ka);
        #pragma unroll
        for (int t = 0; t < 4; t++) CP_ASYNC16(sb + b_doff[t] + buf, g_xh + b_soff[t] + kb);
        CP_COMMIT();
    }

    int cstage = 0;
    for (int s = 0; s < 32; s++) {
        if (s < 29)      { CP_WAIT(3); }
        else if (s == 29){ CP_WAIT(2); }
        else if (s == 30){ CP_WAIT(1); }
        else             { CP_WAIT(0); }
        __syncthreads();

        if (s < 28) {
            int pst = cstage + 4; if (pst >= NSTAGE) pst -= NSTAGE;
            uint32_t buf = (uint32_t)pst * ST_BYTES;
            uint32_t ka = (uint32_t)(s + 4) * 32;
            size_t kb = (size_t)(s + 4) * 32 * NCOL;
            #pragma unroll
            for (int t = 0; t < 4; t++) CP_ASYNC16(sb + a_doff[t] + buf, g_Wc_h + a_soff[t] + ka);
            #pragma unroll
            for (int t = 0; t < 4; t++) CP_ASYNC16(sb + b_doff[t] + buf, g_xh + b_soff[t] + kb);
            CP_COMMIT();
        }

        uint32_t cbuf = (uint32_t)cstage * ST_BYTES;
        #pragma unroll
        for (int ks = 0; ks < 2; ks++) {
            uint32_t bfr[4][4];
            uint32_t baddr = b_lds + cbuf + (uint32_t)(ks * 16) * 272;
            #pragma unroll
            for (int bq = 0; bq < 4; bq++)
                LDSM_X4T(bfr[bq][0], bfr[bq][1], bfr[bq][2], bfr[bq][3], baddr + bq * 32);
            #pragma unroll
            for (int mi = 0; mi < 4; mi++) {
                uint32_t ah[4];
                uint32_t aaddr = a_lds + cbuf + (uint32_t)(mi * 16) * 80 + ks * 32;
                LDSM_X4(ah[0], ah[1], ah[2], ah[3], aaddr);
                #pragma unroll
                for (int bq = 0; bq < 4; bq++) {
                    MMA16816(acc[mi][bq * 2 + 0], ah, bfr[bq][0], bfr[bq][1]);
                    MMA16816(acc[mi][bq * 2 + 1], ah, bfr[bq][2], bfr[bq][3]);
                }
            }
        }
        if (++cstage == NSTAGE) cstage = 0;
    }
    __syncthreads();

    int b0i = n0 / HW2;
    int ncut = (b0i + 1) * HW2;
    int b1i = (ncut < n0 + 128) ? b0i + 1 : b0i;
    int c0i = cidx[b0i], c1i = cidx[b1i];
    int r0 = lane >> 2;
    int colE = (lane & 3) * 2;

    float accE[8], accO[8];
    #pragma unroll
    for (int nj = 0; nj < 8; nj++) { accE[nj] = 0.f; accO[nj] = 0.f; }
    #pragma unroll
    for (int mi = 0; mi < 4; mi++) {
        int mA = m0 + wm * 64 + mi * 16 + r0;
        int mB = mA + 8;
        float biA = g_bi[mA], biB = g_bi[mB];
        float a0A = g_attr1[c0i * 512 + mA], a1A = g_attr1[c1i * 512 + mA];
        float a0B = g_attr1[c0i * 512 + mB], a1B = g_attr1[c1i * 512 + mB];
        #pragma unroll
        for (int nj = 0; nj < 8; nj++) {
            int colg = n0 + wn * 64 + nj * 8 + colE;
            float awAe = (colg < ncut) ? a0A : a1A;
            float awBe = (colg < ncut) ? a0B : a1B;
            float awAo = (colg + 1 < ncut) ? a0A : a1A;
            float awBo = (colg + 1 < ncut) ? a0B : a1B;
            accE[nj] += awAe * ftanh(acc[mi][nj][0] + biA) + awBe * ftanh(acc[mi][nj][2] + biB);
            accO[nj] += awAo * ftanh(acc[mi][nj][1] + biA) + awBo * ftanh(acc[mi][nj][3] + biB);
        }
    }
    #pragma unroll
    for (int off = 4; off <= 16; off <<= 1) {
        #pragma unroll
        for (int nj = 0; nj < 8; nj++) {
            accE[nj] += __shfl_xor_sync(0xffffffffu, accE[nj], off);
            accO[nj] += __shfl_xor_sync(0xffffffffu, accO[nj], off);
        }
    }
    float* sred = (float*)smem;
    if (lane < 4) {
        #pragma unroll
        for (int nj = 0; nj < 8; nj++) {
            sred[wid * 64 + nj * 8 + colE]     = accE[nj];
            sred[wid * 64 + nj * 8 + colE + 1] = accO[nj];
        }
    }
    __syncthreads();
    if (tid < 128) {
        int wn2 = tid >> 6, cl = tid & 63;
        float t = sred[(wn2 * 2) * 64 + cl] + sred[(wn2 * 2 + 1) * 64 + cl];
        atomicAdd(&g_attlog[n0 + tid], t);
    }
}

// ====== launch 5: softmax -> g_attp; also write attr2 tail of G1 input ======
__global__ void softmax_kernel(const int* __restrict__ cidx) {
    int b = blockIdx.x, tid = threadIdx.x;
    __shared__ float sh[256];
    float v = (tid < HW2) ? g_attlog[b * HW2 + tid] * 0.044194173824159216f : -1e30f;
    sh[tid] = v;
    __syncthreads();
    for (int s = 128; s; s >>= 1) {
        if (tid < s) sh[tid] = fmaxf(sh[tid], sh[tid + s]);
        __syncthreads();
    }
    float mx = sh[0];
    __syncthreads();
    float e = (tid < HW2) ? __expf(v - mx) : 0.f;
    sh[tid] = e;
    __syncthreads();
    for (int s = 128; s; s >>= 1) {
        if (tid < s) sh[tid] += sh[tid + s];
        __syncthreads();
    }
    float inv = 1.f / sh[0];
    if (tid < HW2) g_attp[b * HW2 + tid] = e * inv;
    // attr2 tail of concat G1 input
    int ci = cidx[b];
    for (int j = tid; j < 512; j += 256) {
        float a = g_attr2[ci * 512 + j];
        __half h, l;
        split16(a, h, l);
        g_in1h[b * 1536 + 1024 + j] = h;
        g_in1l[b * 1536 + 1024 + j] = l;
    }
}

// ====== launch 6: feat, k-major over g_xh rows (contiguous fp16 reads) ======
// grid 1024 (one CTA per k); each warp handles 64 batches; p streamed from L2.
__global__ void __launch_bounds__(256) featk_kernel() {
    int k = blockIdx.x;
    int warp = threadIdx.x >> 5, lane = threadIdx.x & 31;
    const __half* row = g_xh + (size_t)k * NCOL;
    for (int b = warp; b < BATCH; b += 8) {
        const __half* rb = row + b * HW2;
        const float* pb = g_attp + b * HW2;
        float sum = 0.f;
        #pragma unroll
        for (int ch = lane; ch < 49; ch += 32) {
            uint2 u = *(const uint2*)(rb + ch * 4);
            float2 f01 = __half22float2(*(__half2*)&u.x);
            float2 f23 = __half22float2(*(__half2*)&u.y);
            int hw = ch * 4;
            sum = fmaf(f01.x, pb[hw + 0], sum);
            sum = fmaf(f01.y, pb[hw + 1], sum);
            sum = fmaf(f23.x, pb[hw + 2], sum);
            sum = fmaf(f23.y, pb[hw + 3], sum);
        }
        #pragma unroll
        for (int off = 16; off; off >>= 1)
            sum += __shfl_down_sync(0xffffffffu, sum, off);
        if (lane == 0) {
            g_feat[b * 1024 + k] = sum;
            __half h, l;
            split16(sum, h, l);
            g_in1h[b * 1536 + k] = h;
            g_in1l[b * 1536 + k] = l;
        }
    }
}

// =========== HMMA tail GEMM: C = act(A @ W^T + bias), 3-product split =======
#define GT_STAGE 15360
template <int EPI, int N, int K>
__global__ void __launch_bounds__(128, 4) gemmH_kernel(const float* __restrict__ bias,
                                                       float* __restrict__ outp) {
    const __half* Ah = (EPI == 0) ? g_in1h : (EPI == 1) ? g_h1h : g_fmh;
    const __half* Al = (EPI == 0) ? g_in1l : (EPI == 1) ? g_h1l : g_fml;
    const __half* Wh = (EPI == 0) ? g_w1h : (EPI == 1) ? g_w2h : g_w3h;
    const __half* Wl = (EPI == 0) ? g_w1l : (EPI == 1) ? g_w2l : g_w3l;

    extern __shared__ char smem[];
    uint32_t sb = smem_u32(smem);
    int tid = threadIdx.x, wid = tid >> 5, lane = tid & 31;
    int n0 = blockIdx.x * 64;
    int m0 = blockIdx.y * 32;

    int aRow = tid >> 2, aCh = tid & 3;
    const __half* srcAh = Ah + (size_t)(m0 + aRow) * K + aCh * 8;
    const __half* srcAl = Al + (size_t)(m0 + aRow) * K + aCh * 8;
    uint32_t dstAh = (uint32_t)(aRow * 80 + aCh * 16);
    uint32_t dstAl = 2560 + dstAh;
    const __half* srcWh0 = Wh + (size_t)(n0 + aRow) * K + aCh * 8;
    const __half* srcWh1 = Wh + (size_t)(n0 + 32 + aRow) * K + aCh * 8;
    const __half* srcWl0 = Wl + (size_t)(n0 + aRow) * K + aCh * 8;
    const __half* srcWl1 = Wl + (size_t)(n0 + 32 + aRow) * K + aCh * 8;
    uint32_t dstWh0 = 5120 + (uint32_t)(aRow * 80 + aCh * 16);
    uint32_t dstWh1 = dstWh0 + 32 * 80;
    uint32_t dstWl0 = dstWh0 + 5120;
    uint32_t dstWl1 = dstWh1 + 5120;

    float acc[2][2][4];
    #pragma unroll
    for (int mi = 0; mi < 2; mi++)
        #pragma unroll
        for (int nj = 0; nj < 2; nj++)
            #pragma unroll
            for (int r = 0; r < 4; r++) acc[mi][nj][r] = 0.f;

    uint32_t a_lds = sb + (uint32_t)(lane & 15) * 80 + ((lane >> 4) & 1) * 16;
    uint32_t w_lds = sb + 5120 + (uint32_t)(wid * 16 + (lane & 15)) * 80 + ((lane >> 4) & 1) * 16;

    const int NC = K / 32;
    #pragma unroll
    for (int st = 0; st < 2; st++) {
        uint32_t buf = (uint32_t)st * GT_STAGE;
        uint32_t ka = (uint32_t)st * 32;
        CP_ASYNC16(dstAh + sb + buf, srcAh + ka);
        CP_ASYNC16(dstAl + sb + buf, srcAl + ka);
        CP_ASYNC16(dstWh0 + sb + buf, srcWh0 + ka);
        CP_ASYNC16(dstWh1 + sb + buf, srcWh1 + ka);
        CP_ASYNC16(dstWl0 + sb + buf, srcWl0 + ka);
        CP_ASYNC16(dstWl1 + sb + buf, srcWl1 + ka);
        CP_COMMIT();
    }

    int cstage = 0;
    for (int s = 0; s < NC; s++) {
        if (s < NC - 1) { CP_WAIT(1); } else { CP_WAIT(0); }
        __syncthreads();

        if (s < NC - 2) {
            int pst = cstage + 2; if (pst >= 3) pst -= 3;
            uint32_t buf = (uint32_t)pst * GT_STAGE;
            uint32_t ka = (uint32_t)(s + 2) * 32;
            CP_ASYNC16(dstAh + sb + buf, srcAh + ka);
            CP_ASYNC16(dstAl + sb + buf, srcAl + ka);
            CP_ASYNC16(dstWh0 + sb + buf, srcWh0 + ka);
            CP_ASYNC16(dstWh1 + sb + buf, srcWh1 + ka);
            CP_ASYNC16(dstWl0 + sb + buf, srcWl0 + ka);
            CP_ASYNC16(dstWl1 + sb + buf, srcWl1 + ka);
            CP_COMMIT();
        }

        uint32_t cbuf = (uint32_t)cstage * GT_STAGE;
        #pragma unroll
        for (int ks = 0; ks < 2; ks++) {
            uint32_t wh[4], wl[4];
            uint32_t waddr = w_lds + cbuf + ks * 32;
            LDSM_X4(wh[0], wh[1], wh[2], wh[3], waddr);
            LDSM_X4(wl[0], wl[1], wl[2], wl[3], waddr + 5120);
            #pragma unroll
            for (int mi = 0; mi < 2; mi++) {
                uint32_t ah[4], al[4];
                uint32_t aaddr = a_lds + cbuf + (uint32_t)(mi * 16) * 80 + ks * 32;
                LDSM_X4(ah[0], ah[1], ah[2], ah[3], aaddr);
                LDSM_X4(al[0], al[1], al[2], al[3], aaddr + 2560);
                MMA16816(acc[mi][0], ah, wh[0], wh[2]);
                MMA16816(acc[mi][1], ah, wh[1], wh[3]);
                MMA16816(acc[mi][0], ah, wl[0], wl[2]);
                MMA16816(acc[mi][1], ah, wl[1], wl[3]);
                MMA16816(acc[mi][0], al, wh[0], wh[2]);
                MMA16816(acc[mi][1], al, wh[1], wh[3]);
            }
        }
        if (++cstage == 3) cstage = 0;
    }

    int r0 = lane >> 2;
    int cb = (lane & 3) * 2;
    #pragma unroll
    for (int nj = 0; nj < 2; nj++) {
        int gcol = n0 + wid * 16 + nj * 8 + cb;
        float bv0 = bias[gcol], bv1 = bias[gcol + 1];
        #pragma unroll
        for (int mi = 0; mi < 2; mi++) {
            #pragma unroll
            for (int rh = 0; rh < 2; rh++) {
                int row = m0 + mi * 16 + r0 + rh * 8;
                float v0 = acc[mi][nj][rh * 2 + 0] + bv0;
                float v1 = acc[mi][nj][rh * 2 + 1] + bv1;
                if (EPI == 0) {
                    v0 = fmaxf(v0, 0.f); v1 = fmaxf(v1, 0.f);
                    __half h0, l0, h1, l1;
                    split16(v0, h0, l0); split16(v1, h1, l1);
                    *(__half2*)(g_h1h + (size_t)row * N + gcol) = __halves2half2(h0, h1);
                    *(__half2*)(g_h1l + (size_t)row * N + gcol) = __halves2half2(l0, l1);
                } else if (EPI == 1) {
                    float s0 = 1.f / (1.f + __expf(-v0));
                    float s1 = 1.f / (1.f + __expf(-v1));
                    float p0 = s0 * g_feat[(size_t)row * 1024 + gcol];
                    float p1 = s1 * g_feat[(size_t)row * 1024 + gcol + 1];
                    __half h0, l0, h1, l1;
                    split16(p0, h0, l0); split16(p1, h1, l1);
                    *(__half2*)(g_fmh + (size_t)row * N + gcol) = __halves2half2(h0, h1);
                    *(__half2*)(g_fml + (size_t)row * N + gcol) = __halves2half2(l0, l1);
                } else {
                    *(float2*)(outp + (size_t)row * N + gcol) = make_float2(v0, v1);
                }
            }
        }
    }
}

// ---------------- row-wise L2 normalize in place ----------------------------
__global__ void l2norm_kernel(float* __restrict__ out) {
    int b = blockIdx.x, tid = threadIdx.x;
    __shared__ float sh[256];
    float s = 0.f;
    for (int i = tid; i < EMBD; i += 256) {
        float v = out[(size_t)b * EMBD + i];
        s = fmaf(v, v, s);
    }
    sh[tid] = s;
    __syncthreads();
    for (int st = 128; st; st >>= 1) {
        if (tid < st) sh[tid] += sh[tid + st];
        __syncthreads();
    }
    float inv = 1.f / sqrtf(sh[0]);
    for (int i = tid; i < EMBD; i += 256) out[(size_t)b * EMBD + i] *= inv;
}

// ---------------- launch ----------------------------------------------------
extern "C" void kernel_launch(void* const* d_in, const int* in_sizes, int n_in,
                              void* d_out, int out_size) {
    const float* x        = (const float*)d_in[0];
    const int*   c        = (const int*)  d_in[1];
    const float* attr_emb = (const float*)d_in[2];
    const float* Wt1      = (const float*)d_in[3];
    const float* bt1      = (const float*)d_in[4];
    const float* Wc       = (const float*)d_in[5];
    const float* bc       = (const float*)d_in[6];
    const float* bn_gamma = (const float*)d_in[7];
    const float* bn_beta  = (const float*)d_in[8];
    const float* bn_mean  = (const float*)d_in[9];
    const float* bn_var   = (const float*)d_in[10];
    const float* Wt2      = (const float*)d_in[11];
    const float* bt2      = (const float*)d_in[12];
    const float* W1       = (const float*)d_in[13];
    const float* b1       = (const float*)d_in[14];
    const float* W2       = (const float*)d_in[15];
    const float* b2       = (const float*)d_in[16];
    const float* Wf       = (const float*)d_in[17];
    const float* bf       = (const float*)d_in[18];
    float* out = (float*)d_out;

    static bool attr_set = false;
    if (!attr_set) {
        cudaFuncSetAttribute(conv_att_hmma, cudaFuncAttributeMaxDynamicSharedMemorySize, CONV_SMEM);
        attr_set = true;
    }

    prep_kernel<<<512 + 2304, 256>>>(Wc, bc, bn_gamma, bn_beta, bn_mean, bn_var, W1, W2, Wf); // 1
    attr_kernel<<<dim3(8, 8), 256>>>(attr_emb, Wt1, bt1, Wt2, bt2);                           // 2
    x_prep_kernel<<<BATCH * CIN * 49 / 256, 256>>>(x);                                        // 3
    conv_att_hmma<<<dim3(4, NCOL / 128), 128, CONV_SMEM>>>(c);                                // 4 <- ncu
    softmax_kernel<<<BATCH, 256>>>(c);                                                        // 5
    featk_kernel<<<CIN, 256>>>();                                                             // 6
    gemmH_kernel<0, 512, 1536><<<dim3(512 / 64, BATCH / 32), 128, 3 * GT_STAGE>>>(b1, nullptr);
    gemmH_kernel<1, 1024, 512><<<dim3(1024 / 64, BATCH / 32), 128, 3 * GT_STAGE>>>(b2, nullptr);
    gemmH_kernel<2, 1024, 1024><<<dim3(1024 / 64, BATCH / 32), 128, 3 * GT_STAGE>>>(bf, out);
    l2norm_kernel<<<BATCH, 256>>>(out);
}